// round 9
// baseline (speedup 1.0000x reference)
#include <cuda_runtime.h>
#include <cuda_bf16.h>
#include <cstdint>

#define NN 50000
#define EE 500000
#define FIN 388
#define KP1 416    // FIN padded to multiple of 32
#define ME (EE+NN) // 550000 edge rows (incl self-loops)

typedef __nv_bfloat16 bf16;

// ---------------- static scratch (no allocation allowed) ----------------
__device__ __align__(16) bf16 g_xh   [(size_t)NN*KP1];
__device__ __align__(16) bf16 g_Wlr1h[KP1*1024];            // [Wl1 | Wr1]
__device__ __align__(16) bf16 g_xlr1 [(size_t)NN*1024];     // [xl1 | xr1]
__device__ __align__(16) bf16 g_h1h  [(size_t)NN*512];
__device__ __align__(16) bf16 g_Wlr2h[512*2048];            // [Wl2 | Wr2]
__device__ __align__(16) bf16 g_xlr2 [(size_t)NN*2048];     // [xl2 | xr2]
__device__ __align__(16) bf16 g_We12h[32*1536];             // [We1 | We2]
__device__ __align__(16) bf16 g_eah  [(size_t)ME*32];
__device__ __align__(16) bf16 g_ee12 [(size_t)ME*1536];     // [ee1 | ee2] per edge

__device__ float g_h2 [(size_t)NN*128];
__device__ float g_loopattr[(size_t)NN*16];
__device__ int   g_cnt[NN];
__device__ int   g_offs[NN+1];
__device__ int   g_cursor[NN];
__device__ int   g_csrsrc[EE];
__device__ int   g_csreid[EE];

// ---------------- conversions to bf16 ----------------
__global__ void k_padcols(const float* __restrict__ in, bf16* __restrict__ out,
                          int ci, int co, long n){
    long t = (long)blockIdx.x * blockDim.x + threadIdx.x;
    if (t >= n * co) return;
    long r = t / co; int c = (int)(t - r * co);
    out[t] = (c < ci) ? __float2bfloat16_rn(in[r * ci + c]) : __float2bfloat16_rn(0.f);
}
// pack [L | R] side by side: out [ro][2*cols], rows >= ri zero-padded
__global__ void k_pad2(const float* __restrict__ L, const float* __restrict__ R,
                       bf16* __restrict__ out, int ri, int ro, int cols){
    int t = blockIdx.x * blockDim.x + threadIdx.x;
    if (t >= ro * 2 * cols) return;
    int r = t / (2*cols), c = t - r * 2*cols;
    float v = 0.f;
    if (r < ri) v = (c < cols) ? L[r*cols + c] : R[r*cols + (c - cols)];
    out[t] = __float2bfloat16_rn(v);
}
// pack We12 [32][1536]: rows 0..15 = [We1 row | We2 row], rows 16..31 zero
__global__ void k_padWe12(const float* __restrict__ We1, const float* __restrict__ We2){
    int t = blockIdx.x * blockDim.x + threadIdx.x;
    if (t >= 32*1536) return;
    int r = t / 1536, c = t - r * 1536;
    float v = 0.f;
    if (r < 16) v = (c < 512) ? We1[r*512 + c] : We2[r*1024 + (c - 512)];
    g_We12h[t] = __float2bfloat16_rn(v);
}

// ---------------- CSR construction ----------------
__global__ void k_cnt(const int* __restrict__ ei){
    int e = blockIdx.x * blockDim.x + threadIdx.x;
    if (e < EE) atomicAdd(&g_cnt[ei[EE + e]], 1);
}

__global__ void k_scan(){
    const int C = (NN + 1023) / 1024;
    int t = threadIdx.x, lane = t & 31, w = t >> 5;
    int s = 0;
    for (int i = 0; i < C; i++){ int idx = t*C + i; if (idx < NN) s += g_cnt[idx]; }
    int v = s;
    #pragma unroll
    for (int o = 1; o < 32; o <<= 1){ int u = __shfl_up_sync(~0u, v, o); if (lane >= o) v += u; }
    __shared__ int ws[32];
    if (lane == 31) ws[w] = v;
    __syncthreads();
    if (w == 0){
        int u2 = ws[lane];
        #pragma unroll
        for (int o = 1; o < 32; o <<= 1){ int u = __shfl_up_sync(~0u, u2, o); if (lane >= o) u2 += u; }
        ws[lane] = u2;
    }
    __syncthreads();
    int pref = v - s + (w > 0 ? ws[w-1] : 0);
    for (int i = 0; i < C; i++){
        int idx = t*C + i;
        if (idx < NN){ g_offs[idx] = pref; g_cursor[idx] = pref; pref += g_cnt[idx]; }
    }
    if (t == 1023) g_offs[NN] = pref;
}

__global__ void k_scatter(const int* __restrict__ ei){
    int e = blockIdx.x * blockDim.x + threadIdx.x;
    if (e >= EE) return;
    int s = ei[e], d = ei[EE + e];
    int pos = atomicAdd(&g_cursor[d], 1);
    g_csrsrc[pos] = s;
    g_csreid[pos] = e;
}

// loop_attr = mean of incoming edge_attr, gathered over CSR (no atomics)
__global__ void k_loopattr(const float* __restrict__ ea){
    int n = blockIdx.x * 8 + (threadIdx.x >> 5);
    if (n >= NN) return;
    int l = threadIdx.x & 31, ep = l >> 4, k = l & 15;
    int e0 = g_offs[n], deg = g_offs[n+1] - e0;
    float s = 0.f;
    for (int e = ep; e < deg; e += 2)
        s += ea[(size_t)g_csreid[e0 + e]*16 + k];
    s += __shfl_xor_sync(~0u, s, 16);
    if (l < 16) g_loopattr[n*16 + l] = s / fmaxf((float)deg, 1.f);
}

// build bf16 edge-attr matrix [ME][32] (cols 16..31 zero; rows EE.. = loops)
__global__ void k_eah(const float* __restrict__ ea){
    long t = (long)blockIdx.x * blockDim.x + threadIdx.x;
    if (t >= (long)ME*32) return;
    long e = t >> 5; int k = (int)(t & 31);
    float v = 0.f;
    if (k < 16) v = (e < EE) ? ea[e*16 + k] : g_loopattr[(e - EE)*16 + k];
    g_eah[t] = __float2bfloat16_rn(v);
}

// ---------------- bf16 tensor-core GEMM body, cp.async 3-stage ----------------
__device__ __forceinline__ void ldsm4(uint32_t* r, const void* p){
    unsigned a = (unsigned)__cvta_generic_to_shared(p);
    asm volatile("ldmatrix.sync.aligned.m8n8.x4.shared.b16 {%0,%1,%2,%3}, [%4];"
      : "=r"(r[0]), "=r"(r[1]), "=r"(r[2]), "=r"(r[3]) : "r"(a));
}
__device__ __forceinline__ void ldsm4t(uint32_t* r, const void* p){
    unsigned a = (unsigned)__cvta_generic_to_shared(p);
    asm volatile("ldmatrix.sync.aligned.m8n8.x4.trans.shared.b16 {%0,%1,%2,%3}, [%4];"
      : "=r"(r[0]), "=r"(r[1]), "=r"(r[2]), "=r"(r[3]) : "r"(a));
}
__device__ __forceinline__ void mma_bf16(float* c, const uint32_t* a, const uint32_t* b){
    asm volatile("mma.sync.aligned.m16n8k16.row.col.f32.bf16.bf16.f32 "
        "{%0,%1,%2,%3}, {%4,%5,%6,%7}, {%8,%9}, {%0,%1,%2,%3};"
        : "+f"(c[0]), "+f"(c[1]), "+f"(c[2]), "+f"(c[3])
        : "r"(a[0]), "r"(a[1]), "r"(a[2]), "r"(a[3]), "r"(b[0]), "r"(b[1]));
}
__device__ __forceinline__ void cpa16(unsigned dst, const void* src, int sz){
    asm volatile("cp.async.cg.shared.global [%0], [%1], 16, %2;"
                 :: "r"(dst), "l"(src), "r"(sz));
}
__device__ __forceinline__ unsigned aswz(unsigned off){   // Swizzle<3,4,3> on 64B rows
    return off ^ (((off >> 7) & 7) << 4);
}

// 128x128x32 tile, 8 warps (64x32 warp tile), 3-stage cp.async pipeline.
__device__ __forceinline__ void gemm_body(
    char* smem_raw, const bf16* __restrict__ A, const bf16* __restrict__ B,
    bf16* __restrict__ C, int M, int N, int K, int bxi, int byi)
{
    const int tid  = threadIdx.x;
    const int lane = tid & 31, warp = tid >> 5;
    const int wm = (warp & 1) * 64;
    const int wn = (warp >> 1) * 32;
    const int bm = byi * 128, bn = bxi * 128;

    const int a_r = tid >> 1, a_cc0 = (tid & 1) * 2;
    const int gm = bm + a_r;
    const bool aok = (gm < M);
    const bf16* aptr = A + (size_t)(aok ? gm : 0) * K + a_cc0 * 8;
    const int a_sz = aok ? 16 : 0;
    const unsigned a_sw0 = aswz(a_r * 64 + a_cc0 * 16);
    const unsigned a_sw1 = aswz(a_r * 64 + (a_cc0 + 1) * 16);

    const int b_r = tid >> 3, b_g0 = (tid & 7) * 2;
    const bf16* bptr = B + (size_t)b_r * N + bn + b_g0 * 8;
    const unsigned b_sw0 = (unsigned)(b_r * 256 + ((b_g0     ^ (b_r & 7)) * 16));
    const unsigned b_sw1 = (unsigned)(b_r * 256 + (((b_g0+1) ^ (b_r & 7)) * 16));

    unsigned smem_base = (unsigned)__cvta_generic_to_shared(smem_raw);

    int arow_b[4];
    #pragma unroll
    for (int mt = 0; mt < 4; mt++) arow_b[mt] = (wm + mt*16 + (lane & 15)) * 64;
    const int a_ksel = (lane >> 4);
    const int b_kk_l = lane & 15;
    const int b_ng0  = (wn >> 3) + (lane >> 4);

    float acc[4][4][4];
    #pragma unroll
    for (int i=0;i<4;i++) for (int j=0;j<4;j++) for (int q=0;q<4;q++) acc[i][j][q]=0.f;

    const int niter = K / 32;

    #pragma unroll
    for (int ps = 0; ps < 2; ps++){
        if (ps < niter){
            unsigned as = smem_base + ps * 8192;
            unsigned bs = smem_base + 24576 + ps * 8192;
            int k0 = ps * 32;
            cpa16(as + a_sw0, aptr + k0, a_sz);
            cpa16(as + a_sw1, aptr + k0 + 8, a_sz);
            cpa16(bs + b_sw0, bptr + (size_t)k0 * N, 16);
            cpa16(bs + b_sw1, bptr + (size_t)k0 * N + 8, 16);
        }
        asm volatile("cp.async.commit_group;" ::: "memory");
    }

    for (int it = 0; it < niter; it++){
        asm volatile("cp.async.wait_group 1;" ::: "memory");
        __syncthreads();

        int ldk = it + 2;
        if (ldk < niter){
            int stg = ldk % 3;
            unsigned as = smem_base + stg * 8192;
            unsigned bs = smem_base + 24576 + stg * 8192;
            int k0 = ldk * 32;
            cpa16(as + a_sw0, aptr + k0, a_sz);
            cpa16(as + a_sw1, aptr + k0 + 8, a_sz);
            cpa16(bs + b_sw0, bptr + (size_t)k0 * N, 16);
            cpa16(bs + b_sw1, bptr + (size_t)k0 * N + 8, 16);
        }
        asm volatile("cp.async.commit_group;" ::: "memory");

        int buf = it % 3;
        const char* as = smem_raw + buf * 8192;
        const bf16* bs = (const bf16*)(smem_raw + 24576 + buf * 8192);

        #pragma unroll
        for (int s = 0; s < 2; s++){
            uint32_t af[4][4];
            #pragma unroll
            for (int mt = 0; mt < 4; mt++){
                unsigned off = aswz((unsigned)(arow_b[mt] + (s*2 + a_ksel) * 16));
                ldsm4(af[mt], as + off);
            }
            int kk = s * 16 + b_kk_l;
            uint32_t bfr[2][4];
            #pragma unroll
            for (int p = 0; p < 2; p++){
                int sg = ((b_ng0 + p * 2) ^ (kk & 7));
                ldsm4t(bfr[p], bs + kk * 128 + sg * 8);
            }
            #pragma unroll
            for (int mt = 0; mt < 4; mt++)
                #pragma unroll
                for (int p = 0; p < 2; p++){
                    mma_bf16(acc[mt][p*2+0], af[mt], &bfr[p][0]);
                    mma_bf16(acc[mt][p*2+1], af[mt], &bfr[p][2]);
                }
        }
    }

    #pragma unroll
    for (int mt = 0; mt < 4; mt++) {
        int r0 = bm + wm + mt * 16 + (lane >> 2);
        #pragma unroll
        for (int nt = 0; nt < 4; nt++) {
            int cc = bn + wn + nt * 8 + 2 * (lane & 3);
            if (r0 < M)
                *(__nv_bfloat162*)&C[(size_t)r0 * N + cc] =
                    __floats2bfloat162_rn(acc[mt][nt][0], acc[mt][nt][1]);
            if (r0 + 8 < M)
                *(__nv_bfloat162*)&C[(size_t)(r0 + 8) * N + cc] =
                    __floats2bfloat162_rn(acc[mt][nt][2], acc[mt][nt][3]);
        }
    }
}

__global__ void __launch_bounds__(256, 2)
k_hgemm(const bf16* __restrict__ A, const bf16* __restrict__ B, bf16* __restrict__ C,
        int M, int N, int K)
{
    __shared__ __align__(16) char smem_raw[49152];
    gemm_body(smem_raw, A, B, C, M, N, K, blockIdx.x, blockIdx.y);
}

// MEGA: layer-1 node GEMM (tensor-bound) + ee12 GEMM (DRAM-bound), interleaved 1:16.
// seg0: xlr1 = xh @ Wlr1h  -> 3128 blocks (nx=8,  391 rows)
// seg1: ee12 = eah @ We12h -> 51564 blocks (nx=12, 4297 rows)
#define NB0 3128
#define NB1 51564
#define NBBASE (NB0*17)          // 53176
#define NBTOT  (NB0 + NB1)       // 54692
__global__ void __launch_bounds__(256, 2)
k_mega()
{
    __shared__ __align__(16) char smem_raw[49152];
    int idx = blockIdx.x;
    int seg, j;
    if (idx < NBBASE){
        int a = idx / 17, r = idx - a * 17;
        if (r == 0){ seg = 0; j = a; }
        else       { seg = 1; j = a * 16 + (r - 1); }
    } else { seg = 1; j = NB0 * 16 + (idx - NBBASE); }

    if (seg == 0)
        gemm_body(smem_raw, g_xh, g_Wlr1h, g_xlr1, NN, 1024, KP1, j & 7, j >> 3);
    else
        gemm_body(smem_raw, g_eah, g_We12h, g_ee12, ME, 1536, 32, j % 12, j / 12);
}

// ---------------- fused node-centric GAT layer, online softmax ----------------
// xlr rows are [xl | xr] stride 2*HD; ee rows at stride ESTR with offset EOFF.
template<int HD, int THREADS, int REDW, bool CONCAT, int ESTR, int EOFF>
__global__ void __launch_bounds__(THREADS)
k_node(const bf16* __restrict__ xlr, const bf16* __restrict__ ee,
       const float* __restrict__ att, const float* __restrict__ bias,
       bf16* __restrict__ out_b, float* __restrict__ out_f)
{
    const int n = blockIdx.x;
    const int t = threadIdx.x, w = t >> 5, l = t & 31;
    const int q = 32*w + l;   // uint2 index (4 features)

    float xr4[4], at4[4];
    {
        uint2 xv = ((const uint2*)(xlr + (size_t)n * (2*HD) + HD))[q];
        __nv_bfloat162 p0 = *(__nv_bfloat162*)&xv.x;
        __nv_bfloat162 p1 = *(__nv_bfloat162*)&xv.y;
        xr4[0] = __low2float(p0); xr4[1] = __high2float(p0);
        xr4[2] = __low2float(p1); xr4[3] = __high2float(p1);
        float4 a = *(const float4*)&att[4*q];
        at4[0] = a.x; at4[1] = a.y; at4[2] = a.z; at4[3] = a.w;
    }

    float m = -1e30f, den = 0.f, acc[4] = {0.f, 0.f, 0.f, 0.f};

    const int e0 = g_offs[n];
    const int deg = g_offs[n+1] - e0;

    int s1 = (0 < deg) ? g_csrsrc[e0] : n;
    int i1 = (0 < deg) ? g_csreid[e0] : (EE + n);
    uint2 xv1 = ((const uint2*)(xlr + (size_t)s1 * (2*HD)))[q];
    uint2 ev1 = ((const uint2*)(ee + (size_t)i1 * ESTR + EOFF))[q];
    int s2 = (1 < deg) ? g_csrsrc[e0 + 1] : n;
    int i2 = (1 < deg) ? g_csreid[e0 + 1] : (EE + n);

    for (int e = 0; e <= deg; e++){
        uint2 xv2, ev2;
        if (e + 1 <= deg){
            xv2 = ((const uint2*)(xlr + (size_t)s2 * (2*HD)))[q];
            ev2 = ((const uint2*)(ee + (size_t)i2 * ESTR + EOFF))[q];
        }
        int s3 = (e + 2 < deg) ? g_csrsrc[e0 + e + 2] : n;
        int i3 = (e + 2 < deg) ? g_csreid[e0 + e + 2] : (EE + n);

        __nv_bfloat162 x0 = *(__nv_bfloat162*)&xv1.x;
        __nv_bfloat162 x1 = *(__nv_bfloat162*)&xv1.y;
        __nv_bfloat162 e0v = *(__nv_bfloat162*)&ev1.x;
        __nv_bfloat162 e1v = *(__nv_bfloat162*)&ev1.y;
        float xf[4] = {__low2float(x0), __high2float(x0),
                       __low2float(x1), __high2float(x1)};
        float ef[4] = {__low2float(e0v), __high2float(e0v),
                       __low2float(e1v), __high2float(e1v)};
        float p = 0.f;
        #pragma unroll
        for (int i = 0; i < 4; i++){
            float v = xf[i] + xr4[i] + ef[i];
            v = v > 0.f ? v : 0.2f * v;
            p += at4[i] * v;
        }
        #pragma unroll
        for (int o = REDW/2; o > 0; o >>= 1)
            p += __shfl_xor_sync(~0u, p, o);
        float mn = fmaxf(m, p);
        float sc = __expf(m - mn);
        float pv = __expf(p - mn);
        m = mn;
        den = den * sc + pv;
        #pragma unroll
        for (int i = 0; i < 4; i++)
            acc[i] = acc[i] * sc + pv * xf[i];

        xv1 = xv2; ev1 = ev2; s2 = s3; i2 = i3;
    }

    float inv = 1.f / den;
    if (CONCAT){
        __nv_bfloat162* ob = (__nv_bfloat162*)(out_b + (size_t)n * HD);
        float4 b = *(const float4*)&bias[4*q];
        float o0 = tanhf(acc[0]*inv + b.x);
        float o1 = tanhf(acc[1]*inv + b.y);
        float o2 = tanhf(acc[2]*inv + b.z);
        float o3 = tanhf(acc[3]*inv + b.w);
        ob[2*q]     = __floats2bfloat162_rn(o0, o1);
        ob[2*q + 1] = __floats2bfloat162_rn(o2, o3);
    } else {
        __shared__ float sm[8][128];
        #pragma unroll
        for (int i = 0; i < 4; i++) sm[w][4*l + i] = acc[i] * inv;
        __syncthreads();
        if (t < 128){
            float s = 0.f;
            #pragma unroll
            for (int h = 0; h < 8; h++) s += sm[h][t];
            out_f[(size_t)n*128 + t] = tanhf(s * 0.125f + bias[t]);
        }
    }
}

// ---------------- single-step LSTM (h0=c0=0) + FC: warp per node ----------------
__global__ void k_lstm(const float* __restrict__ W_ih, const float* __restrict__ b_ih,
                       const float* __restrict__ b_hh, const float* __restrict__ fcW,
                       const float* __restrict__ fcb, float* __restrict__ out)
{
    __shared__ float sh[8][128];
    int w = threadIdx.x >> 5, lane = threadIdx.x & 31;
    int node = blockIdx.x * 8 + w;
    if (node >= NN) return;
    const float* hr = g_h2 + (size_t)node * 128;
    for (int i = lane; i < 128; i += 32) sh[w][i] = hr[i];
    __syncwarp();

    float gates[3];
    const int rows[3] = {lane, 64 + lane, 96 + lane};
    #pragma unroll
    for (int q = 0; q < 3; q++) {
        const float4* wr = (const float4*)(W_ih + (size_t)rows[q] * 128);
        const float4* hv = (const float4*)sh[w];
        float s = 0.f;
        #pragma unroll 8
        for (int k = 0; k < 32; k++) {
            float4 wv = wr[k], xv = hv[k];
            s += wv.x*xv.x + wv.y*xv.y + wv.z*xv.z + wv.w*xv.w;
        }
        gates[q] = s + b_ih[rows[q]] + b_hh[rows[q]];
    }
    float ci = 1.f / (1.f + __expf(-gates[0]));
    float cg = tanhf(gates[1]);
    float co = 1.f / (1.f + __expf(-gates[2]));
    float c  = ci * cg;
    float hid = co * tanhf(c);
    float y = hid * fcW[lane];
    #pragma unroll
    for (int off = 16; off > 0; off >>= 1)
        y += __shfl_xor_sync(0xffffffffu, y, off);
    if (lane == 0) out[node] = y + fcb[0];
}

// ---------------- launch ----------------
extern "C" void kernel_launch(void* const* d_in, const int* in_sizes, int n_in,
                              void* d_out, int out_size)
{
    const float* x    = (const float*)d_in[0];
    const int*   ei   = (const int*)  d_in[1];
    const float* ea   = (const float*)d_in[2];
    const float* Wl1  = (const float*)d_in[3];
    const float* Wr1  = (const float*)d_in[4];
    const float* We1  = (const float*)d_in[5];
    const float* att1 = (const float*)d_in[6];
    const float* b1   = (const float*)d_in[7];
    const float* Wl2  = (const float*)d_in[8];
    const float* Wr2  = (const float*)d_in[9];
    const float* We2  = (const float*)d_in[10];
    const float* att2 = (const float*)d_in[11];
    const float* b2   = (const float*)d_in[12];
    const float* W_ih = (const float*)d_in[13];
    /* d_in[14] = W_hh: unused (h0 = 0) */
    const float* b_ih = (const float*)d_in[15];
    const float* b_hh = (const float*)d_in[16];
    const float* fcW  = (const float*)d_in[17];
    const float* fcb  = (const float*)d_in[18];
    float* out = (float*)d_out;

    void* p;
    bf16 *xh, *Wlr1h, *xlr1, *h1h, *Wlr2h, *xlr2, *ee12;
    int* cnt;
    cudaGetSymbolAddress(&p, g_xh);     xh    = (bf16*)p;
    cudaGetSymbolAddress(&p, g_Wlr1h);  Wlr1h = (bf16*)p;
    cudaGetSymbolAddress(&p, g_xlr1);   xlr1  = (bf16*)p;
    cudaGetSymbolAddress(&p, g_h1h);    h1h   = (bf16*)p;
    cudaGetSymbolAddress(&p, g_Wlr2h);  Wlr2h = (bf16*)p;
    cudaGetSymbolAddress(&p, g_xlr2);   xlr2  = (bf16*)p;
    cudaGetSymbolAddress(&p, g_ee12);   ee12  = (bf16*)p;
    cudaGetSymbolAddress(&p, g_cnt);    cnt   = (int*)p;
    float* h2; cudaGetSymbolAddress(&p, g_h2); h2 = (float*)p;

    cudaMemsetAsync(cnt, 0, NN * sizeof(int));

    // conversions (independent)
    k_padcols<<<(int)(((long)NN*KP1 + 255)/256), 256>>>(x, xh, FIN, KP1, NN);
    k_pad2<<<(KP1*1024 + 255)/256, 256>>>(Wl1, Wr1, Wlr1h, FIN, KP1, 512);
    k_pad2<<<(512*2048 + 255)/256, 256>>>(Wl2, Wr2, Wlr2h, 512, 512, 1024);
    k_padWe12<<<(32*1536 + 255)/256, 256>>>(We1, We2);
    // CSR + self-loop attrs
    k_cnt<<<(EE + 255)/256, 256>>>(ei);
    k_scan<<<1, 1024>>>();
    k_scatter<<<(EE + 255)/256, 256>>>(ei);
    k_loopattr<<<(NN + 7)/8, 256>>>(ea);
    k_eah<<<(int)(((long)ME*32 + 255)/256), 256>>>(ea);
    // MEGA: layer-1 node GEMM + combined ee GEMM, interleaved
    k_mega<<<NBTOT, 256>>>();
    // fused GAT layer 1
    k_node<512, 128, 16, true, 1536, 0><<<NN, 128>>>(xlr1, ee12, att1, b1, h1h, nullptr);
    // layer-2 node GEMM
    dim3 g2(2048/128, (NN + 127)/128);
    k_hgemm<<<g2, 256>>>(h1h, Wlr2h, xlr2, NN, 2048, 512);
    // fused GAT layer 2 (ee at offset 512 within ee12 rows; uint2 offset = 512/4 handled by EOFF elems)
    k_node<1024, 256, 32, false, 1536, 512><<<NN, 256>>>(xlr2, ee12, att2, b2, nullptr, h2);

    k_lstm<<<(NN + 7)/8, 256>>>(W_ih, b_ih, b_hh, fcW, fcb, out);
}

// round 11
// speedup vs baseline: 1.0578x; 1.0578x over previous
#include <cuda_runtime.h>
#include <cuda_bf16.h>
#include <cstdint>

#define NN 50000
#define EE 500000
#define FIN 388
#define KP1 416    // FIN padded to multiple of 32
#define ME (EE+NN) // 550000 edge rows (incl self-loops)

typedef __nv_bfloat16 bf16;

// ---------------- static scratch (no allocation allowed) ----------------
__device__ __align__(16) bf16 g_xh   [(size_t)NN*KP1];
__device__ __align__(16) bf16 g_Wlr1h[KP1*1024];            // [Wl1 | Wr1]
__device__ __align__(16) bf16 g_xlr1 [(size_t)NN*1024];     // [xl1 | xr1]
__device__ __align__(16) bf16 g_h1h  [(size_t)NN*512];
__device__ __align__(16) bf16 g_Wlr2h[512*2048];            // [Wl2 | Wr2]
__device__ __align__(16) bf16 g_xlr2 [(size_t)NN*2048];     // [xl2 | xr2]
__device__ __align__(16) bf16 g_We1h [32*512];
__device__ __align__(16) bf16 g_We2h [32*1024];
__device__ __align__(16) bf16 g_eah  [(size_t)ME*32];
__device__ __align__(16) bf16 g_ee1  [(size_t)ME*512];
__device__ __align__(16) bf16 g_ee2  [(size_t)ME*1024];

__device__ float g_h2 [(size_t)NN*128];
__device__ float g_loopattr[(size_t)NN*16];
__device__ int   g_cnt[NN];
__device__ int   g_offs[NN+1];
__device__ int   g_cursor[NN];
__device__ int   g_csrsrc[EE];
__device__ int   g_csreid[EE];

// ---------------- conversions to bf16 ----------------
__global__ void k_padcols(const float* __restrict__ in, bf16* __restrict__ out,
                          int ci, int co, long n){
    long t = (long)blockIdx.x * blockDim.x + threadIdx.x;
    if (t >= n * co) return;
    long r = t / co; int c = (int)(t - r * co);
    out[t] = (c < ci) ? __float2bfloat16_rn(in[r * ci + c]) : __float2bfloat16_rn(0.f);
}
__global__ void k_padrows(const float* __restrict__ in, bf16* __restrict__ out,
                          int ri, int ro, int cols){
    int t = blockIdx.x * blockDim.x + threadIdx.x;
    if (t >= ro * cols) return;
    int r = t / cols;
    out[t] = (r < ri) ? __float2bfloat16_rn(in[t]) : __float2bfloat16_rn(0.f);
}
// pack [L | R] side by side: out [ro][2*cols], rows >= ri zero-padded
__global__ void k_pad2(const float* __restrict__ L, const float* __restrict__ R,
                       bf16* __restrict__ out, int ri, int ro, int cols){
    int t = blockIdx.x * blockDim.x + threadIdx.x;
    if (t >= ro * 2 * cols) return;
    int r = t / (2*cols), c = t - r * 2*cols;
    float v = 0.f;
    if (r < ri) v = (c < cols) ? L[r*cols + c] : R[r*cols + (c - cols)];
    out[t] = __float2bfloat16_rn(v);
}

// ---------------- CSR construction ----------------
__global__ void k_cnt(const int* __restrict__ ei){
    int e = blockIdx.x * blockDim.x + threadIdx.x;
    if (e < EE) atomicAdd(&g_cnt[ei[EE + e]], 1);
}

__global__ void k_scan(){
    const int C = (NN + 1023) / 1024;
    int t = threadIdx.x, lane = t & 31, w = t >> 5;
    int s = 0;
    for (int i = 0; i < C; i++){ int idx = t*C + i; if (idx < NN) s += g_cnt[idx]; }
    int v = s;
    #pragma unroll
    for (int o = 1; o < 32; o <<= 1){ int u = __shfl_up_sync(~0u, v, o); if (lane >= o) v += u; }
    __shared__ int ws[32];
    if (lane == 31) ws[w] = v;
    __syncthreads();
    if (w == 0){
        int u2 = ws[lane];
        #pragma unroll
        for (int o = 1; o < 32; o <<= 1){ int u = __shfl_up_sync(~0u, u2, o); if (lane >= o) u2 += u; }
        ws[lane] = u2;
    }
    __syncthreads();
    int pref = v - s + (w > 0 ? ws[w-1] : 0);
    for (int i = 0; i < C; i++){
        int idx = t*C + i;
        if (idx < NN){ g_offs[idx] = pref; g_cursor[idx] = pref; pref += g_cnt[idx]; }
    }
    if (t == 1023) g_offs[NN] = pref;
}

__global__ void k_scatter(const int* __restrict__ ei){
    int e = blockIdx.x * blockDim.x + threadIdx.x;
    if (e >= EE) return;
    int s = ei[e], d = ei[EE + e];
    int pos = atomicAdd(&g_cursor[d], 1);
    g_csrsrc[pos] = s;
    g_csreid[pos] = e;
}

// loop_attr = mean of incoming edge_attr, gathered over CSR (no atomics)
__global__ void k_loopattr(const float* __restrict__ ea){
    int n = blockIdx.x * 8 + (threadIdx.x >> 5);
    if (n >= NN) return;
    int l = threadIdx.x & 31, ep = l >> 4, k = l & 15;
    int e0 = g_offs[n], deg = g_offs[n+1] - e0;
    float s = 0.f;
    for (int e = ep; e < deg; e += 2)
        s += ea[(size_t)g_csreid[e0 + e]*16 + k];
    s += __shfl_xor_sync(~0u, s, 16);
    if (l < 16) g_loopattr[n*16 + l] = s / fmaxf((float)deg, 1.f);
}

// build bf16 edge-attr matrix [ME][32] (cols 16..31 zero; rows EE.. = loops)
__global__ void k_eah(const float* __restrict__ ea){
    long t = (long)blockIdx.x * blockDim.x + threadIdx.x;
    if (t >= (long)ME*32) return;
    long e = t >> 5; int k = (int)(t & 31);
    float v = 0.f;
    if (k < 16) v = (e < EE) ? ea[e*16 + k] : g_loopattr[(e - EE)*16 + k];
    g_eah[t] = __float2bfloat16_rn(v);
}

// ---------------- bf16 tensor-core GEMM, cp.async 3-stage ----------------
__device__ __forceinline__ void ldsm4(uint32_t* r, const void* p){
    unsigned a = (unsigned)__cvta_generic_to_shared(p);
    asm volatile("ldmatrix.sync.aligned.m8n8.x4.shared.b16 {%0,%1,%2,%3}, [%4];"
      : "=r"(r[0]), "=r"(r[1]), "=r"(r[2]), "=r"(r[3]) : "r"(a));
}
__device__ __forceinline__ void ldsm4t(uint32_t* r, const void* p){
    unsigned a = (unsigned)__cvta_generic_to_shared(p);
    asm volatile("ldmatrix.sync.aligned.m8n8.x4.trans.shared.b16 {%0,%1,%2,%3}, [%4];"
      : "=r"(r[0]), "=r"(r[1]), "=r"(r[2]), "=r"(r[3]) : "r"(a));
}
__device__ __forceinline__ void mma_bf16(float* c, const uint32_t* a, const uint32_t* b){
    asm volatile("mma.sync.aligned.m16n8k16.row.col.f32.bf16.bf16.f32 "
        "{%0,%1,%2,%3}, {%4,%5,%6,%7}, {%8,%9}, {%0,%1,%2,%3};"
        : "+f"(c[0]), "+f"(c[1]), "+f"(c[2]), "+f"(c[3])
        : "r"(a[0]), "r"(a[1]), "r"(a[2]), "r"(a[3]), "r"(b[0]), "r"(b[1]));
}
__device__ __forceinline__ void cpa16(unsigned dst, const void* src, int sz){
    asm volatile("cp.async.cg.shared.global [%0], [%1], 16, %2;"
                 :: "r"(dst), "l"(src), "r"(sz));
}
__device__ __forceinline__ unsigned aswz(unsigned off){   // Swizzle<3,4,3> on 64B rows
    return off ^ (((off >> 7) & 7) << 4);
}

// 128x128x32 tile, 8 warps (64x32 warp tile), 3-stage cp.async pipeline.
__global__ void __launch_bounds__(256, 2)
k_hgemm(const bf16* __restrict__ A, const bf16* __restrict__ B, bf16* __restrict__ C,
        int M, int N, int K)   // K % 32 == 0, N % 128 == 0
{
    __shared__ __align__(16) char smem_raw[49152];

    const int tid  = threadIdx.x;
    const int lane = tid & 31, warp = tid >> 5;
    const int wm = (warp & 1) * 64;
    const int wn = (warp >> 1) * 32;
    const int bm = blockIdx.y * 128, bn = blockIdx.x * 128;

    const int a_r = tid >> 1, a_cc0 = (tid & 1) * 2;
    const int gm = bm + a_r;
    const bool aok = (gm < M);
    const bf16* aptr = A + (size_t)(aok ? gm : 0) * K + a_cc0 * 8;
    const int a_sz = aok ? 16 : 0;
    const unsigned a_sw0 = aswz(a_r * 64 + a_cc0 * 16);
    const unsigned a_sw1 = aswz(a_r * 64 + (a_cc0 + 1) * 16);

    const int b_r = tid >> 3, b_g0 = (tid & 7) * 2;
    const bf16* bptr = B + (size_t)b_r * N + bn + b_g0 * 8;
    const unsigned b_sw0 = (unsigned)(b_r * 256 + ((b_g0     ^ (b_r & 7)) * 16));
    const unsigned b_sw1 = (unsigned)(b_r * 256 + (((b_g0+1) ^ (b_r & 7)) * 16));

    unsigned smem_base = (unsigned)__cvta_generic_to_shared(smem_raw);

    int arow_b[4];
    #pragma unroll
    for (int mt = 0; mt < 4; mt++) arow_b[mt] = (wm + mt*16 + (lane & 15)) * 64;
    const int a_ksel = (lane >> 4);
    const int b_kk_l = lane & 15;
    const int b_ng0  = (wn >> 3) + (lane >> 4);

    float acc[4][4][4];
    #pragma unroll
    for (int i=0;i<4;i++) for (int j=0;j<4;j++) for (int q=0;q<4;q++) acc[i][j][q]=0.f;

    const int niter = K / 32;

    #pragma unroll
    for (int ps = 0; ps < 2; ps++){
        if (ps < niter){
            unsigned as = smem_base + ps * 8192;
            unsigned bs = smem_base + 24576 + ps * 8192;
            int k0 = ps * 32;
            cpa16(as + a_sw0, aptr + k0, a_sz);
            cpa16(as + a_sw1, aptr + k0 + 8, a_sz);
            cpa16(bs + b_sw0, bptr + (size_t)k0 * N, 16);
            cpa16(bs + b_sw1, bptr + (size_t)k0 * N + 8, 16);
        }
        asm volatile("cp.async.commit_group;" ::: "memory");
    }

    for (int it = 0; it < niter; it++){
        asm volatile("cp.async.wait_group 1;" ::: "memory");
        __syncthreads();

        int ldk = it + 2;
        if (ldk < niter){
            int stg = ldk % 3;
            unsigned as = smem_base + stg * 8192;
            unsigned bs = smem_base + 24576 + stg * 8192;
            int k0 = ldk * 32;
            cpa16(as + a_sw0, aptr + k0, a_sz);
            cpa16(as + a_sw1, aptr + k0 + 8, a_sz);
            cpa16(bs + b_sw0, bptr + (size_t)k0 * N, 16);
            cpa16(bs + b_sw1, bptr + (size_t)k0 * N + 8, 16);
        }
        asm volatile("cp.async.commit_group;" ::: "memory");

        int buf = it % 3;
        const char* as = smem_raw + buf * 8192;
        const bf16* bs = (const bf16*)(smem_raw + 24576 + buf * 8192);

        #pragma unroll
        for (int s = 0; s < 2; s++){
            uint32_t af[4][4];
            #pragma unroll
            for (int mt = 0; mt < 4; mt++){
                unsigned off = aswz((unsigned)(arow_b[mt] + (s*2 + a_ksel) * 16));
                ldsm4(af[mt], as + off);
            }
            int kk = s * 16 + b_kk_l;
            uint32_t bfr[2][4];
            #pragma unroll
            for (int p = 0; p < 2; p++){
                int sg = ((b_ng0 + p * 2) ^ (kk & 7));
                ldsm4t(bfr[p], bs + kk * 128 + sg * 8);
            }
            #pragma unroll
            for (int mt = 0; mt < 4; mt++)
                #pragma unroll
                for (int p = 0; p < 2; p++){
                    mma_bf16(acc[mt][p*2+0], af[mt], &bfr[p][0]);
                    mma_bf16(acc[mt][p*2+1], af[mt], &bfr[p][2]);
                }
        }
    }

    #pragma unroll
    for (int mt = 0; mt < 4; mt++) {
        int r0 = bm + wm + mt * 16 + (lane >> 2);
        #pragma unroll
        for (int nt = 0; nt < 4; nt++) {
            int cc = bn + wn + nt * 8 + 2 * (lane & 3);
            if (r0 < M)
                *(__nv_bfloat162*)&C[(size_t)r0 * N + cc] =
                    __floats2bfloat162_rn(acc[mt][nt][0], acc[mt][nt][1]);
            if (r0 + 8 < M)
                *(__nv_bfloat162*)&C[(size_t)(r0 + 8) * N + cc] =
                    __floats2bfloat162_rn(acc[mt][nt][2], acc[mt][nt][3]);
        }
    }
}

// ---------------- fused node-centric GAT layer, online softmax ----------------
template<int HD, int THREADS, int REDW, bool CONCAT>
__global__ void __launch_bounds__(THREADS)
k_node(const bf16* __restrict__ xlr, const bf16* __restrict__ ee,
       const float* __restrict__ att, const float* __restrict__ bias,
       bf16* __restrict__ out_b, float* __restrict__ out_f)
{
    const int n = blockIdx.x;
    const int t = threadIdx.x, w = t >> 5, l = t & 31;
    const int q = 32*w + l;   // uint2 index (4 features)

    float xr4[4], at4[4];
    {
        uint2 xv = ((const uint2*)(xlr + (size_t)n * (2*HD) + HD))[q];
        __nv_bfloat162 p0 = *(__nv_bfloat162*)&xv.x;
        __nv_bfloat162 p1 = *(__nv_bfloat162*)&xv.y;
        xr4[0] = __low2float(p0); xr4[1] = __high2float(p0);
        xr4[2] = __low2float(p1); xr4[3] = __high2float(p1);
        float4 a = *(const float4*)&att[4*q];
        at4[0] = a.x; at4[1] = a.y; at4[2] = a.z; at4[3] = a.w;
    }

    float m = -1e30f, den = 0.f, acc[4] = {0.f, 0.f, 0.f, 0.f};

    const int e0 = g_offs[n];
    const int deg = g_offs[n+1] - e0;

    int s1 = (0 < deg) ? g_csrsrc[e0] : n;
    int i1 = (0 < deg) ? g_csreid[e0] : (EE + n);
    uint2 xv1 = ((const uint2*)(xlr + (size_t)s1 * (2*HD)))[q];
    uint2 ev1 = ((const uint2*)(ee + (size_t)i1 * HD))[q];
    int s2 = (1 < deg) ? g_csrsrc[e0 + 1] : n;
    int i2 = (1 < deg) ? g_csreid[e0 + 1] : (EE + n);

    for (int e = 0; e <= deg; e++){
        uint2 xv2, ev2;
        if (e + 1 <= deg){
            xv2 = ((const uint2*)(xlr + (size_t)s2 * (2*HD)))[q];
            ev2 = ((const uint2*)(ee + (size_t)i2 * HD))[q];
        }
        int s3 = (e + 2 < deg) ? g_csrsrc[e0 + e + 2] : n;
        int i3 = (e + 2 < deg) ? g_csreid[e0 + e + 2] : (EE + n);

        __nv_bfloat162 x0 = *(__nv_bfloat162*)&xv1.x;
        __nv_bfloat162 x1 = *(__nv_bfloat162*)&xv1.y;
        __nv_bfloat162 e0v = *(__nv_bfloat162*)&ev1.x;
        __nv_bfloat162 e1v = *(__nv_bfloat162*)&ev1.y;
        float xf[4] = {__low2float(x0), __high2float(x0),
                       __low2float(x1), __high2float(x1)};
        float ef[4] = {__low2float(e0v), __high2float(e0v),
                       __low2float(e1v), __high2float(e1v)};
        float p = 0.f;
        #pragma unroll
        for (int i = 0; i < 4; i++){
            float v = xf[i] + xr4[i] + ef[i];
            v = v > 0.f ? v : 0.2f * v;
            p += at4[i] * v;
        }
        #pragma unroll
        for (int o = REDW/2; o > 0; o >>= 1)
            p += __shfl_xor_sync(~0u, p, o);
        float mn = fmaxf(m, p);
        float sc = __expf(m - mn);
        float pv = __expf(p - mn);
        m = mn;
        den = den * sc + pv;
        #pragma unroll
        for (int i = 0; i < 4; i++)
            acc[i] = acc[i] * sc + pv * xf[i];

        xv1 = xv2; ev1 = ev2; s2 = s3; i2 = i3;
    }

    float inv = 1.f / den;
    if (CONCAT){
        __nv_bfloat162* ob = (__nv_bfloat162*)(out_b + (size_t)n * HD);
        float4 b = *(const float4*)&bias[4*q];
        float o0 = tanhf(acc[0]*inv + b.x);
        float o1 = tanhf(acc[1]*inv + b.y);
        float o2 = tanhf(acc[2]*inv + b.z);
        float o3 = tanhf(acc[3]*inv + b.w);
        ob[2*q]     = __floats2bfloat162_rn(o0, o1);
        ob[2*q + 1] = __floats2bfloat162_rn(o2, o3);
    } else {
        __shared__ float sm[8][128];
        #pragma unroll
        for (int i = 0; i < 4; i++) sm[w][4*l + i] = acc[i] * inv;
        __syncthreads();
        if (t < 128){
            float s = 0.f;
            #pragma unroll
            for (int h = 0; h < 8; h++) s += sm[h][t];
            out_f[(size_t)n*128 + t] = tanhf(s * 0.125f + bias[t]);
        }
    }
}

// ---------------- single-step LSTM (h0=c0=0) + FC: warp per node ----------------
__global__ void k_lstm(const float* __restrict__ W_ih, const float* __restrict__ b_ih,
                       const float* __restrict__ b_hh, const float* __restrict__ fcW,
                       const float* __restrict__ fcb, float* __restrict__ out)
{
    __shared__ float sh[8][128];
    int w = threadIdx.x >> 5, lane = threadIdx.x & 31;
    int node = blockIdx.x * 8 + w;
    if (node >= NN) return;
    const float* hr = g_h2 + (size_t)node * 128;
    for (int i = lane; i < 128; i += 32) sh[w][i] = hr[i];
    __syncwarp();

    float gates[3];
    const int rows[3] = {lane, 64 + lane, 96 + lane};
    #pragma unroll
    for (int q = 0; q < 3; q++) {
        const float4* wr = (const float4*)(W_ih + (size_t)rows[q] * 128);
        const float4* hv = (const float4*)sh[w];
        float s = 0.f;
        #pragma unroll 8
        for (int k = 0; k < 32; k++) {
            float4 wv = wr[k], xv = hv[k];
            s += wv.x*xv.x + wv.y*xv.y + wv.z*xv.z + wv.w*xv.w;
        }
        gates[q] = s + b_ih[rows[q]] + b_hh[rows[q]];
    }
    float ci = 1.f / (1.f + __expf(-gates[0]));
    float cg = tanhf(gates[1]);
    float co = 1.f / (1.f + __expf(-gates[2]));
    float c  = ci * cg;
    float hid = co * tanhf(c);
    float y = hid * fcW[lane];
    #pragma unroll
    for (int off = 16; off > 0; off >>= 1)
        y += __shfl_xor_sync(0xffffffffu, y, off);
    if (lane == 0) out[node] = y + fcb[0];
}

// ---------------- launch (stream fork/join for graph-level overlap) ----------------
extern "C" void kernel_launch(void* const* d_in, const int* in_sizes, int n_in,
                              void* d_out, int out_size)
{
    const float* x    = (const float*)d_in[0];
    const int*   ei   = (const int*)  d_in[1];
    const float* ea   = (const float*)d_in[2];
    const float* Wl1  = (const float*)d_in[3];
    const float* Wr1  = (const float*)d_in[4];
    const float* We1  = (const float*)d_in[5];
    const float* att1 = (const float*)d_in[6];
    const float* b1   = (const float*)d_in[7];
    const float* Wl2  = (const float*)d_in[8];
    const float* Wr2  = (const float*)d_in[9];
    const float* We2  = (const float*)d_in[10];
    const float* att2 = (const float*)d_in[11];
    const float* b2   = (const float*)d_in[12];
    const float* W_ih = (const float*)d_in[13];
    /* d_in[14] = W_hh: unused (h0 = 0) */
    const float* b_ih = (const float*)d_in[15];
    const float* b_hh = (const float*)d_in[16];
    const float* fcW  = (const float*)d_in[17];
    const float* fcb  = (const float*)d_in[18];
    float* out = (float*)d_out;

    void* p;
    bf16 *xh, *Wlr1h, *xlr1, *h1h, *Wlr2h, *xlr2, *We1h, *We2h, *eah, *ee1, *ee2;
    int* cnt;
    cudaGetSymbolAddress(&p, g_xh);     xh    = (bf16*)p;
    cudaGetSymbolAddress(&p, g_Wlr1h);  Wlr1h = (bf16*)p;
    cudaGetSymbolAddress(&p, g_xlr1);   xlr1  = (bf16*)p;
    cudaGetSymbolAddress(&p, g_h1h);    h1h   = (bf16*)p;
    cudaGetSymbolAddress(&p, g_Wlr2h);  Wlr2h = (bf16*)p;
    cudaGetSymbolAddress(&p, g_xlr2);   xlr2  = (bf16*)p;
    cudaGetSymbolAddress(&p, g_We1h);   We1h  = (bf16*)p;
    cudaGetSymbolAddress(&p, g_We2h);   We2h  = (bf16*)p;
    cudaGetSymbolAddress(&p, g_eah);    eah   = (bf16*)p;
    cudaGetSymbolAddress(&p, g_ee1);    ee1   = (bf16*)p;
    cudaGetSymbolAddress(&p, g_ee2);    ee2   = (bf16*)p;
    cudaGetSymbolAddress(&p, g_cnt);    cnt   = (int*)p;
    float* h2; cudaGetSymbolAddress(&p, g_h2); h2 = (float*)p;

    // fork/join infrastructure (created per call; capture-time only, never timed)
    cudaStream_t s1;
    cudaStreamCreate(&s1);
    cudaEvent_t e0, e1, e2;
    cudaEventCreateWithFlags(&e0, cudaEventDisableTiming);
    cudaEventCreateWithFlags(&e1, cudaEventDisableTiming);
    cudaEventCreateWithFlags(&e2, cudaEventDisableTiming);

    // ---- stream 0 (capture origin): memset, then fork ----
    cudaMemsetAsync(cnt, 0, NN * sizeof(int));
    cudaEventRecord(e0, 0);
    cudaStreamWaitEvent(s1, e0, 0);

    // ---- branch B on s1: CSR -> eah -> ee1 GEMM -> ee2 GEMM ----
    k_cnt<<<(EE + 255)/256, 256, 0, s1>>>(ei);
    k_scan<<<1, 1024, 0, s1>>>();
    k_scatter<<<(EE + 255)/256, 256, 0, s1>>>(ei);
    k_loopattr<<<(NN + 7)/8, 256, 0, s1>>>(ea);
    k_eah<<<(int)(((long)ME*32 + 255)/256), 256, 0, s1>>>(ea);
    k_padrows<<<(32*512 + 255)/256, 256, 0, s1>>>(We1, We1h, 16, 32, 512);
    {
        dim3 ge1(512/128, (ME + 127)/128);
        k_hgemm<<<ge1, 256, 0, s1>>>(eah, We1h, ee1, ME, 512, 32);
    }
    cudaEventRecord(e1, s1);
    k_padrows<<<(32*1024 + 255)/256, 256, 0, s1>>>(We2, We2h, 16, 32, 1024);
    {
        dim3 ge2(1024/128, (ME + 127)/128);
        k_hgemm<<<ge2, 256, 0, s1>>>(eah, We2h, ee2, ME, 1024, 32);
    }
    cudaEventRecord(e2, s1);

    // ---- branch A on stream 0: conversions -> node GEMM 1 ----
    k_padcols<<<(int)(((long)NN*KP1 + 255)/256), 256>>>(x, xh, FIN, KP1, NN);
    k_pad2<<<(KP1*1024 + 255)/256, 256>>>(Wl1, Wr1, Wlr1h, FIN, KP1, 512);
    k_pad2<<<(512*2048 + 255)/256, 256>>>(Wl2, Wr2, Wlr2h, 512, 512, 1024);
    {
        dim3 g1(1024/128, (NN + 127)/128);
        k_hgemm<<<g1, 256>>>(xh, Wlr1h, xlr1, NN, 1024, KP1);
    }

    // join ee1 -> fused GAT layer 1 (overlaps with ee2 GEMM on s1)
    cudaStreamWaitEvent(0, e1, 0);
    k_node<512, 128, 16, true><<<NN, 128>>>(xlr1, ee1, att1, b1, h1h, nullptr);

    // node GEMM 2 (tensor-bound; overlaps ee2 GEMM tail)
    {
        dim3 g2(2048/128, (NN + 127)/128);
        k_hgemm<<<g2, 256>>>(h1h, Wlr2h, xlr2, NN, 2048, 512);
    }

    // join ee2 -> fused GAT layer 2 -> LSTM
    cudaStreamWaitEvent(0, e2, 0);
    k_node<1024, 256, 32, false><<<NN, 256>>>(xlr2, ee2, att2, b2, nullptr, h2);
    k_lstm<<<(NN + 7)/8, 256>>>(W_ih, b_ih, b_hh, fcW, fcb, out);
}